// round 1
// baseline (speedup 1.0000x reference)
#include <cuda_runtime.h>
#include <cuda_bf16.h>
#include <cstdint>

// Problem constants
#define BB  32
#define TT  256
#define DD  512
#define MPP 20

constexpr int KC  = 16;        // k-chunk per pipeline stage (one k16 mma step)
constexpr int NKC = DD / KC;   // 32 chunks
constexpr int AS  = 24;        // padded smem row stride (bf16 elems): 48B rows, 16B-aligned, LDSM conflict-free
constexpr int TM  = 128;       // CTA tile rows (t)
constexpr int TN  = 256;       // CTA tile cols (s) == full T

// bf16 scratch (static device arrays: allocation-free per harness rules)
__device__ __nv_bfloat16 g_lt[BB * TT * DD];
__device__ __nv_bfloat16 g_rt[BB * TT * DD];

static __device__ __forceinline__ uint32_t s2u(const void* p) {
    return (uint32_t)__cvta_generic_to_shared(p);
}

// ---------------------------------------------------------------------------
// Kernel 1: fp32 -> bf16 conversion of lt and rt
// ---------------------------------------------------------------------------
__global__ void cvt_kernel(const float* __restrict__ lt, const float* __restrict__ rt) {
    int i = blockIdx.x * blockDim.x + threadIdx.x;  // over n/4 float4 units
    float4 a = reinterpret_cast<const float4*>(lt)[i];
    float4 b = reinterpret_cast<const float4*>(rt)[i];
    __nv_bfloat162* dl = reinterpret_cast<__nv_bfloat162*>(g_lt);
    __nv_bfloat162* dr = reinterpret_cast<__nv_bfloat162*>(g_rt);
    __nv_bfloat162 p;
    p.x = __float2bfloat16(a.x); p.y = __float2bfloat16(a.y); dl[2*i]   = p;
    p.x = __float2bfloat16(a.z); p.y = __float2bfloat16(a.w); dl[2*i+1] = p;
    p.x = __float2bfloat16(b.x); p.y = __float2bfloat16(b.y); dr[2*i]   = p;
    p.x = __float2bfloat16(b.z); p.y = __float2bfloat16(b.w); dr[2*i+1] = p;
}

// ---------------------------------------------------------------------------
// Kernel 2: per (b, m, t-tile): scores = (lt .* km) @ rt^T, max over s, tanh
// Block: 512 threads = 16 warps in a 4(t) x 4(s) grid; warp tile 32x64.
// ---------------------------------------------------------------------------
__global__ __launch_bounds__(512, 1)
void match_kernel(const float* __restrict__ kw, float* __restrict__ out) {
    __shared__ __align__(16) __nv_bfloat16 As[2][TM][AS];
    __shared__ __align__(16) __nv_bfloat16 Bs[2][TN][AS];
    __shared__ __align__(16) __nv_bfloat16 kms[DD];
    __shared__ float redbuf[TM][4];

    const int tid = threadIdx.x;
    const int m   = blockIdx.y;
    const int b   = blockIdx.z;
    const int t0  = blockIdx.x * TM;

    // stage km row m as bf16 (512 threads, 512 elems)
    kms[tid] = __float2bfloat16(kw[m * DD + tid]);
    __syncthreads();

    const __nv_bfloat16* ltb = g_lt + (size_t)(b * TT + t0) * DD;
    const __nv_bfloat16* rtb = g_rt + (size_t)b * TT * DD;

    // global/STS load roles: 4 threads per row, 4 bf16 (uint2) each
    const int lrow = tid >> 2;   // 0..127
    const int lu   = tid & 3;    // 0..3

    const int wid  = tid >> 5;
    const int lane = tid & 31;
    const int wt   = wid >> 2;   // 0..3 : t sub-tile
    const int ws   = wid & 3;    // 0..3 : s sub-tile

    // ldmatrix lane->address mapping
    const int a_r = (lane & 15);                      // A: rows within 16-row mfrag
    const int a_k = (lane >> 4) * 8;                  // A: k half
    const int b_r = (lane & 7) + ((lane >> 4) << 3);  // B: s row within 16-row group
    const int b_k = ((lane >> 3) & 1) * 8;            // B: k half

    float acc[2][8][4];
#pragma unroll
    for (int mi = 0; mi < 2; mi++)
#pragma unroll
        for (int ni = 0; ni < 8; ni++)
#pragma unroll
            for (int r = 0; r < 4; r++) acc[mi][ni][r] = 0.0f;

    uint2 av, bv0, bv1, kv;

    auto ldg_chunk = [&](int k0) {
        av  = *reinterpret_cast<const uint2*>(ltb + lrow * DD + k0 + lu * 4);
        bv0 = *reinterpret_cast<const uint2*>(rtb + lrow * DD + k0 + lu * 4);
        bv1 = *reinterpret_cast<const uint2*>(rtb + (lrow + 128) * DD + k0 + lu * 4);
        kv  = *reinterpret_cast<const uint2*>(&kms[k0 + lu * 4]);
    };

    auto sts_chunk = [&](int buf) {
        __nv_bfloat162 a0 = __hmul2(*reinterpret_cast<__nv_bfloat162*>(&av.x),
                                    *reinterpret_cast<__nv_bfloat162*>(&kv.x));
        __nv_bfloat162 a1 = __hmul2(*reinterpret_cast<__nv_bfloat162*>(&av.y),
                                    *reinterpret_cast<__nv_bfloat162*>(&kv.y));
        *reinterpret_cast<__nv_bfloat162*>(&As[buf][lrow][lu * 4])     = a0;
        *reinterpret_cast<__nv_bfloat162*>(&As[buf][lrow][lu * 4 + 2]) = a1;
        *reinterpret_cast<uint2*>(&Bs[buf][lrow][lu * 4])       = bv0;
        *reinterpret_cast<uint2*>(&Bs[buf][lrow + 128][lu * 4]) = bv1;
    };

    auto compute = [&](int buf) {
        uint32_t a[2][4];
#pragma unroll
        for (int mi = 0; mi < 2; mi++) {
            uint32_t addr = s2u(&As[buf][wt * 32 + mi * 16 + a_r][a_k]);
            asm volatile("ldmatrix.sync.aligned.m8n8.x4.shared.b16 {%0,%1,%2,%3}, [%4];"
                         : "=r"(a[mi][0]), "=r"(a[mi][1]), "=r"(a[mi][2]), "=r"(a[mi][3])
                         : "r"(addr));
        }
        uint32_t bf[8][2];
#pragma unroll
        for (int nj = 0; nj < 4; nj++) {
            uint32_t addr = s2u(&Bs[buf][ws * 64 + nj * 16 + b_r][b_k]);
            uint32_t r0, r1, r2, r3;
            asm volatile("ldmatrix.sync.aligned.m8n8.x4.shared.b16 {%0,%1,%2,%3}, [%4];"
                         : "=r"(r0), "=r"(r1), "=r"(r2), "=r"(r3)
                         : "r"(addr));
            bf[nj * 2][0] = r0; bf[nj * 2][1] = r1;
            bf[nj * 2 + 1][0] = r2; bf[nj * 2 + 1][1] = r3;
        }
#pragma unroll
        for (int mi = 0; mi < 2; mi++)
#pragma unroll
            for (int ni = 0; ni < 8; ni++) {
                asm volatile(
                    "mma.sync.aligned.m16n8k16.row.col.f32.bf16.bf16.f32 "
                    "{%0,%1,%2,%3},{%4,%5,%6,%7},{%8,%9},{%0,%1,%2,%3};"
                    : "+f"(acc[mi][ni][0]), "+f"(acc[mi][ni][1]),
                      "+f"(acc[mi][ni][2]), "+f"(acc[mi][ni][3])
                    : "r"(a[mi][0]), "r"(a[mi][1]), "r"(a[mi][2]), "r"(a[mi][3]),
                      "r"(bf[ni][0]), "r"(bf[ni][1]));
            }
    };

    // pipeline: preload chunk 0
    ldg_chunk(0);
    sts_chunk(0);
    __syncthreads();

    for (int ki = 0; ki < NKC; ki++) {
        const int cur = ki & 1;
        if (ki + 1 < NKC) ldg_chunk((ki + 1) * KC);
        compute(cur);
        if (ki + 1 < NKC) sts_chunk((ki + 1) & 1);
        __syncthreads();
    }

    // Epilogue: max over s (cols), then tanh. Col permutation is irrelevant to max;
    // only the t-row mapping of the C fragment matters.
    const int g   = lane >> 2;
    const int tig = lane & 3;
#pragma unroll
    for (int mi = 0; mi < 2; mi++)
#pragma unroll
        for (int h = 0; h < 2; h++) {
            float mv = -3.0e38f;
#pragma unroll
            for (int ni = 0; ni < 8; ni++)
                mv = fmaxf(mv, fmaxf(acc[mi][ni][h * 2], acc[mi][ni][h * 2 + 1]));
            mv = fmaxf(mv, __shfl_xor_sync(0xffffffffu, mv, 1));
            mv = fmaxf(mv, __shfl_xor_sync(0xffffffffu, mv, 2));
            if (tig == 0)
                redbuf[wt * 32 + mi * 16 + h * 8 + g][ws] = mv;
        }
    __syncthreads();

    if (tid < TM) {
        float mv = fmaxf(fmaxf(redbuf[tid][0], redbuf[tid][1]),
                         fmaxf(redbuf[tid][2], redbuf[tid][3]));
        out[(size_t)(b * TT + t0 + tid) * MPP + m] = tanhf(mv);
    }
}

// ---------------------------------------------------------------------------
// Launch: inputs in metadata order: reps_lt[B,T,D] f32, reps_rt[B,T,D] f32,
// kernel[1,1,1,MP,D] f32. Output [B,T,MP] f32.
// ---------------------------------------------------------------------------
extern "C" void kernel_launch(void* const* d_in, const int* in_sizes, int n_in,
                              void* d_out, int out_size) {
    const float* lt = (const float*)d_in[0];
    const float* rt = (const float*)d_in[1];
    const float* kw = (const float*)d_in[2];
    float* out = (float*)d_out;

    // convert fp32 -> bf16 scratch (n = BB*TT*DD = 4,194,304; /4 per thread)
    const int n4 = (BB * TT * DD) / 4;  // 1,048,576
    cvt_kernel<<<n4 / 256, 256>>>(lt, rt);

    dim3 grid(TT / TM, MPP, BB);  // (2, 20, 32) = 1280 CTAs
    match_kernel<<<grid, 512>>>(kw, out);
}

// round 3
// speedup vs baseline: 1.6268x; 1.6268x over previous
#include <cuda_runtime.h>
#include <cuda_fp16.h>
#include <cstdint>

// Problem constants
#define BB  32
#define TT  256
#define DD  512
#define MPP 20

constexpr int TM     = 128;            // CTA t rows
constexpr int TN     = 256;            // CTA s cols (full T)
constexpr int KC     = 32;             // k per pipeline stage
constexpr int NST    = DD / KC;        // 16 stages of work
constexpr int STAGES = 4;              // cp.async ring depth
constexpr int ROWB   = 80;             // padded smem row bytes (64B data + 16B pad)
constexpr int A_BYTES   = TM * ROWB;              // 10240
constexpr int B_BYTES   = TN * ROWB;              // 20480
constexpr int STG_BYTES = A_BYTES + B_BYTES;      // 30720

constexpr int S_KMS = 0;               // 2*512 halves = 2048 B
constexpr int S_RED = 2048;            // 2*128*4 floats = 4096 B
constexpr int S_BUF = 6144;            // 128B aligned
constexpr int S_TOTAL = S_BUF + STAGES * STG_BYTES;  // 129024 B

// fp16 scratch (static device arrays: allocation-free per harness rules)
__device__ __half g_lt[BB * TT * DD];
__device__ __half g_rt[BB * TT * DD];

static __device__ __forceinline__ uint32_t s2u(const void* p) {
    return (uint32_t)__cvta_generic_to_shared(p);
}

#define CP16(dst, src) \
    asm volatile("cp.async.cg.shared.global [%0], [%1], 16;" :: "r"(dst), "l"(src))

#define LDSM4(r0, r1, r2, r3, addr)                                              \
    asm volatile("ldmatrix.sync.aligned.m8n8.x4.shared.b16 {%0,%1,%2,%3}, [%4];" \
                 : "=r"(r0), "=r"(r1), "=r"(r2), "=r"(r3) : "r"(addr))

#define MMA16816(d0, d1, a0, a1, a2, a3, b0, b1)                                  \
    asm volatile("mma.sync.aligned.m16n8k16.row.col.f16.f16.f16.f16 "             \
                 "{%0,%1},{%2,%3,%4,%5},{%6,%7},{%0,%1};"                         \
                 : "+r"(d0), "+r"(d1)                                             \
                 : "r"(a0), "r"(a1), "r"(a2), "r"(a3), "r"(b0), "r"(b1))

static __device__ __forceinline__ uint32_t hmul2u(uint32_t a, uint32_t b) {
    __half2 r = __hmul2(*reinterpret_cast<__half2*>(&a),
                        *reinterpret_cast<__half2*>(&b));
    return *reinterpret_cast<uint32_t*>(&r);
}

// ---------------------------------------------------------------------------
// Kernel 1: fp32 -> fp16 conversion of lt and rt
// ---------------------------------------------------------------------------
__global__ void cvt_kernel(const float* __restrict__ lt, const float* __restrict__ rt) {
    int i = blockIdx.x * blockDim.x + threadIdx.x;  // over n/4 float4 units
    float4 a = reinterpret_cast<const float4*>(lt)[i];
    float4 b = reinterpret_cast<const float4*>(rt)[i];
    __half2* dl = reinterpret_cast<__half2*>(g_lt);
    __half2* dr = reinterpret_cast<__half2*>(g_rt);
    dl[2*i]   = __floats2half2_rn(a.x, a.y);
    dl[2*i+1] = __floats2half2_rn(a.z, a.w);
    dr[2*i]   = __floats2half2_rn(b.x, b.y);
    dr[2*i+1] = __floats2half2_rn(b.z, b.w);
}

// ---------------------------------------------------------------------------
// Kernel 2: one CTA = (b, t-tile 128, m-pair). scores = (lt .* km) @ rt^T,
// fp16 HMMA with fp16 accumulation; raw lt fragments scaled by km in regs so
// B fragments are reused across both m. 4-stage cp.async pipeline.
// 16 warps in 4(t) x 4(s) grid; warp tile 32t x 64s x 2m.
// ---------------------------------------------------------------------------
__global__ __launch_bounds__(512, 1)
void match_kernel(const float* __restrict__ kw, float* __restrict__ out) {
    extern __shared__ __align__(128) char smem[];
    const int tid = threadIdx.x;
    const int b   = blockIdx.z;
    const int m0  = blockIdx.y * 2;
    const int t0  = blockIdx.x * TM;
    const uint32_t sbase = s2u(smem);
    const uint32_t sbuf  = sbase + S_BUF;

    // stage km rows (m0, m0+1) as fp16
    __half* kms = reinterpret_cast<__half*>(smem + S_KMS);
    for (int e = tid; e < 2 * DD; e += 512) {
        int mi = e >> 9, c = e & (DD - 1);
        kms[e] = __float2half_rn(kw[(m0 + mi) * DD + c]);
    }

    const __half* ltb = g_lt + (size_t)(b * TT + t0) * DD;
    const __half* rtb = g_rt + (size_t)b * TT * DD;

    const int wid  = tid >> 5;
    const int lane = tid & 31;
    const int wt   = wid >> 2;   // 0..3 : t sub-tile (32 rows)
    const int ws   = wid & 3;    // 0..3 : s sub-tile (64 cols)

    // ldmatrix address bases (bytes into stage buffer)
    const uint32_t aoff = (uint32_t)(wt * 32 + (lane & 15)) * ROWB + (lane >> 4) * 16;
    const uint32_t boff = (uint32_t)(ws * 64 + (lane & 7) + ((lane >> 4) << 3)) * ROWB
                        + ((lane >> 3) & 1) * 16;
    const int c0 = (lane & 3) * 2;   // k column base of this thread's A frag elems

    uint32_t acc[2][2][8][2];        // [m][t-frag][n-frag][reg] fp16x2
#pragma unroll
    for (int mi = 0; mi < 2; mi++)
#pragma unroll
        for (int ti = 0; ti < 2; ti++)
#pragma unroll
            for (int ni = 0; ni < 8; ni++) {
                acc[mi][ti][ni][0] = 0u; acc[mi][ti][ni][1] = 0u;
            }

    auto issue = [&](int st) {
        const uint32_t sb = sbuf + (st % STAGES) * STG_BYTES;
        const int k0 = st * KC;
#pragma unroll
        for (int i = 0; i < 3; i++) {
            int c = tid + i * 512;   // 0..1535 : 512 A chunks then 1024 B chunks
            if (c < 512) {
                int row = c >> 2, sub = c & 3;
                CP16(sb + row * ROWB + sub * 16, ltb + row * DD + k0 + sub * 8);
            } else {
                int c2 = c - 512, row = c2 >> 2, sub = c2 & 3;
                CP16(sb + A_BYTES + row * ROWB + sub * 16, rtb + row * DD + k0 + sub * 8);
            }
        }
    };

    auto compute = [&](int st) {
        const uint32_t sb = sbuf + (st % STAGES) * STG_BYTES;
#pragma unroll
        for (int kk = 0; kk < 2; kk++) {
            const int kb = st * KC + kk * 16;
            uint32_t bfr[8][2];
#pragma unroll
            for (int nj = 0; nj < 4; nj++) {
                uint32_t r0, r1, r2, r3;
                LDSM4(r0, r1, r2, r3, sb + A_BYTES + boff + nj * (16 * ROWB) + kk * 32);
                bfr[nj * 2][0] = r0;     bfr[nj * 2][1] = r1;
                bfr[nj * 2 + 1][0] = r2; bfr[nj * 2 + 1][1] = r3;
            }
            uint32_t ar[2][4];
#pragma unroll
            for (int ti = 0; ti < 2; ti++)
                LDSM4(ar[ti][0], ar[ti][1], ar[ti][2], ar[ti][3],
                      sb + aoff + ti * (16 * ROWB) + kk * 32);
#pragma unroll
            for (int mi = 0; mi < 2; mi++) {
                const uint32_t kp0 = *reinterpret_cast<const uint32_t*>(&kms[mi * DD + kb + c0]);
                const uint32_t kp1 = *reinterpret_cast<const uint32_t*>(&kms[mi * DD + kb + c0 + 8]);
#pragma unroll
                for (int ti = 0; ti < 2; ti++) {
                    uint32_t a0 = hmul2u(ar[ti][0], kp0);
                    uint32_t a1 = hmul2u(ar[ti][1], kp0);
                    uint32_t a2 = hmul2u(ar[ti][2], kp1);
                    uint32_t a3 = hmul2u(ar[ti][3], kp1);
#pragma unroll
                    for (int ni = 0; ni < 8; ni++)
                        MMA16816(acc[mi][ti][ni][0], acc[mi][ti][ni][1],
                                 a0, a1, a2, a3, bfr[ni][0], bfr[ni][1]);
                }
            }
        }
    };

    // Prologue: 3 stages in flight
    issue(0); asm volatile("cp.async.commit_group;" ::: "memory");
    issue(1); asm volatile("cp.async.commit_group;" ::: "memory");
    issue(2); asm volatile("cp.async.commit_group;" ::: "memory");

    for (int ki = 0; ki < NST; ki++) {
        asm volatile("cp.async.wait_group 2;" ::: "memory");
        __syncthreads();           // stage ki visible to all; also fences buffer reuse
        compute(ki);
        if (ki + 3 < NST) issue(ki + 3);   // writes buf (ki-1)%4: safe post-barrier
        asm volatile("cp.async.commit_group;" ::: "memory");
    }

    // Epilogue: max over s (all permutations irrelevant to max), tanh, store
    float* red = reinterpret_cast<float*>(smem + S_RED);
    __syncthreads();
#pragma unroll
    for (int mi = 0; mi < 2; mi++)
#pragma unroll
        for (int ti = 0; ti < 2; ti++)
#pragma unroll
            for (int h = 0; h < 2; h++) {
                __half2 v = *reinterpret_cast<__half2*>(&acc[mi][ti][0][h]);
#pragma unroll
                for (int ni = 1; ni < 8; ni++)
                    v = __hmax2(v, *reinterpret_cast<__half2*>(&acc[mi][ti][ni][h]));
                float fm = fmaxf(__low2float(v), __high2float(v));
                fm = fmaxf(fm, __shfl_xor_sync(0xffffffffu, fm, 1));
                fm = fmaxf(fm, __shfl_xor_sync(0xffffffffu, fm, 2));
                if ((lane & 3) == 0) {
                    int row = wt * 32 + ti * 16 + h * 8 + (lane >> 2);
                    red[(mi * 128 + row) * 4 + ws] = fm;
                }
            }
    __syncthreads();
    if (tid < 256) {
        const int mi = tid >> 7, row = tid & 127;
        const float* r = &red[(mi * 128 + row) * 4];
        float v = fmaxf(fmaxf(r[0], r[1]), fmaxf(r[2], r[3]));
        out[(size_t)(b * TT + t0 + row) * MPP + (m0 + mi)] = tanhf(v);
    }
}

// ---------------------------------------------------------------------------
// Launch: inputs: reps_lt[B,T,D] f32, reps_rt[B,T,D] f32, kernel[1,1,1,MP,D] f32.
// Output [B,T,MP] f32.
// ---------------------------------------------------------------------------
extern "C" void kernel_launch(void* const* d_in, const int* in_sizes, int n_in,
                              void* d_out, int out_size) {
    const float* lt = (const float*)d_in[0];
    const float* rt = (const float*)d_in[1];
    const float* kw = (const float*)d_in[2];
    float* out = (float*)d_out;

    const int n4 = (BB * TT * DD) / 4;  // 1,048,576 float4 units
    cvt_kernel<<<n4 / 256, 256>>>(lt, rt);

    cudaFuncSetAttribute(match_kernel,
                         cudaFuncAttributeMaxDynamicSharedMemorySize, S_TOTAL);
    dim3 grid(TT / TM, MPP / 2, BB);  // (2, 10, 32) = 640 CTAs
    match_kernel<<<grid, 512, S_TOTAL>>>(kw, out);
}